// round 8
// baseline (speedup 1.0000x reference)
#include <cuda_runtime.h>
#include <cuda_bf16.h>
#include <math.h>

// ---------------------------------------------------------------------------
// DiscriminativeLoss, fused single-launch persistent kernel.
//   binary:   pred [2, N], labels in [0,2)   (B=4)
//   instance: pred [5, N], labels in [0,6)   (B=4)
// out[0] = mean_b binary_loss, out[1] = mean_b instance_loss
//
// One wave: 592 blocks = 148 SMs x 4. Each block handles the SAME data chunk
// in phase 1 (segment sums) and phase 2 (hinge variance), separated by a
// grid-wide software barrier. Phase 2 iterates in REVERSE so the L1-resident
// MRU tail of the chunk hits first; the rest hits L2 (all 75.5 MB resident).
// ---------------------------------------------------------------------------

#define DELTA_V   0.5f
#define TWO_DD    6.0f
#define PREG      0.001f

#define NB_BIN    49
#define NB_INST   99
#define TOTAL_BLOCKS (4 * (NB_BIN + NB_INST))   // 592

__device__ float    g_sum[2][4][8][8];   // [type][b][k][d]
__device__ float    g_cnt[2][4][8];      // [type][b][k]
__device__ float    g_var2[2][4];        // [type][b]
__device__ unsigned g_bar1;              // phase-1 barrier counter
__device__ unsigned g_done;              // phase-2 completion counter

__device__ __forceinline__ float fsqrt_approx(float x) {
    float r;
    asm("sqrt.approx.f32 %0, %1;" : "=f"(r) : "f"(x));
    return r;
}

struct Work { int type, b, xi, nblk; };
__device__ __forceinline__ Work map_block(int bid) {
    Work w;
    if (bid < NB_BIN * 4) {
        w.type = 0; w.b = bid / NB_BIN; w.xi = bid % NB_BIN; w.nblk = NB_BIN;
    } else {
        int j = bid - NB_BIN * 4;
        w.type = 1; w.b = j / NB_INST; w.xi = j % NB_INST; w.nblk = NB_INST;
    }
    return w;
}

// ---------------------------------------------------------------------------
// Phase 1: segment sums + counts (register accumulators, predicated FMA)
// ---------------------------------------------------------------------------
template <int D, int K>
__device__ __forceinline__ void reduce_impl(const float* __restrict__ pred,
                                            const int* __restrict__ labels,
                                            int N, int xi, int nblk,
                                            float* __restrict__ gsum,
                                            float* __restrict__ gcnt) {
    float s[K * D];
    float c[K];
#pragma unroll
    for (int i = 0; i < K * D; i++) s[i] = 0.f;
#pragma unroll
    for (int k = 0; k < K; k++) c[k] = 0.f;

    const int n4 = N >> 2;
    const int4* lab4 = (const int4*)labels;
    const int stride = nblk * 256;

    for (int i = xi * 256 + threadIdx.x; i < n4; i += stride) {
        int4 L = lab4[i];
        float4 v[D];
#pragma unroll
        for (int d = 0; d < D; d++)
            v[d] = ((const float4*)(pred + (size_t)d * N))[i];

        int ls[4] = {L.x, L.y, L.z, L.w};
#pragma unroll
        for (int e = 0; e < 4; e++) {
            int lab = ls[e];
#pragma unroll
            for (int k = 0; k < K; k++) {
                float m = (lab == k) ? 1.f : 0.f;
                c[k] += m;
#pragma unroll
                for (int d = 0; d < D; d++) {
                    float val = (e == 0) ? v[d].x : (e == 1) ? v[d].y
                               : (e == 2) ? v[d].z : v[d].w;
                    s[k * D + d] += m * val;
                }
            }
        }
    }

#pragma unroll
    for (int o = 16; o > 0; o >>= 1) {
#pragma unroll
        for (int i = 0; i < K * D; i++) s[i] += __shfl_xor_sync(0xffffffffu, s[i], o);
#pragma unroll
        for (int k = 0; k < K; k++) c[k] += __shfl_xor_sync(0xffffffffu, c[k], o);
    }

    __shared__ float sh[K * D + K];
    for (int i = threadIdx.x; i < K * D + K; i += blockDim.x) sh[i] = 0.f;
    __syncthreads();
    if ((threadIdx.x & 31) == 0) {
#pragma unroll
        for (int i = 0; i < K * D; i++) atomicAdd(&sh[i], s[i]);
#pragma unroll
        for (int k = 0; k < K; k++) atomicAdd(&sh[K * D + k], c[k]);
    }
    __syncthreads();
    if (threadIdx.x < K * D) {
        int k = threadIdx.x / D, d = threadIdx.x % D;
        atomicAdd(&gsum[k * 8 + d], sh[threadIdx.x]);
    }
    if (threadIdx.x < K) atomicAdd(&gcnt[threadIdx.x], sh[K * D + threadIdx.x]);
}

// ---------------------------------------------------------------------------
// Phase 2: hinge variance, scalar smem means, REVERSE iteration (L1 MRU).
// ---------------------------------------------------------------------------
template <int D, int K>
__device__ __forceinline__ void var_impl(const float* __restrict__ pred,
                                         const int* __restrict__ labels,
                                         int N, int xi, int nblk,
                                         const float* __restrict__ gsum,
                                         const float* __restrict__ gcnt,
                                         float* __restrict__ gvar) {
    __shared__ float sm[K * D];
    __shared__ float sinv[K];
    if (threadIdx.x < K * D) {
        int k = threadIdx.x / D, d = threadIdx.x % D;
        sm[threadIdx.x] = gsum[k * 8 + d] / gcnt[k];
    }
    if (threadIdx.x < K) sinv[threadIdx.x] = 1.f / gcnt[threadIdx.x];
    __syncthreads();

    float acc = 0.f;

    const int n4 = N >> 2;
    const int4* lab4 = (const int4*)labels;
    const int stride = nblk * 256;
    const int first = xi * 256 + threadIdx.x;

    if (first < n4) {
        int count = (n4 - first + stride - 1) / stride;
        int i = first + (count - 1) * stride;      // start at MRU end
        for (; i >= first; i -= stride) {
            int4 L = lab4[i];
            float4 v[D];
#pragma unroll
            for (int d = 0; d < D; d++)
                v[d] = ((const float4*)(pred + (size_t)d * N))[i];

            int ls[4] = {L.x, L.y, L.z, L.w};
#pragma unroll
            for (int e = 0; e < 4; e++) {
                int lab = ls[e];
                float sq = 0.f;
#pragma unroll
                for (int d = 0; d < D; d++) {
                    float val = (e == 0) ? v[d].x : (e == 1) ? v[d].y
                               : (e == 2) ? v[d].z : v[d].w;
                    float df = sm[lab * D + d] - val;
                    sq += df * df;
                }
                float dist = fsqrt_approx(sq);
                float h = fmaxf(dist - DELTA_V, 0.f);
                acc += h * h * sinv[lab];
            }
        }
    }

#pragma unroll
    for (int o = 16; o > 0; o >>= 1)
        acc += __shfl_xor_sync(0xffffffffu, acc, o);

    __shared__ float shv;
    if (threadIdx.x == 0) shv = 0.f;
    __syncthreads();
    if ((threadIdx.x & 31) == 0) atomicAdd(&shv, acc);
    __syncthreads();
    if (threadIdx.x == 0) atomicAdd(gvar, shv);
}

// ---------------------------------------------------------------------------
// Fused kernel: phase1 -> grid barrier -> phase2 -> last-block finalize.
// ---------------------------------------------------------------------------
__global__ __launch_bounds__(256, 4) void fused_kernel(
    const float* __restrict__ binL, const int* __restrict__ binLab,
    const float* __restrict__ instL, const int* __restrict__ instLab, int N,
    float* __restrict__ out) {
    Work w = map_block(blockIdx.x);

    // ---------------- phase 1 ----------------
    if (w.type == 0) {
        reduce_impl<2, 2>(binL + (size_t)w.b * 2 * N, binLab + (size_t)w.b * N,
                          N, w.xi, w.nblk, &g_sum[0][w.b][0][0], &g_cnt[0][w.b][0]);
    } else {
        reduce_impl<5, 6>(instL + (size_t)w.b * 5 * N, instLab + (size_t)w.b * N,
                          N, w.xi, w.nblk, &g_sum[1][w.b][0][0], &g_cnt[1][w.b][0]);
    }

    // ---------------- grid-wide barrier ----------------
    __threadfence();                 // release g_sum/g_cnt atomics
    __syncthreads();                 // all warps of this block arrived
    if (threadIdx.x == 0) {
        atomicAdd(&g_bar1, 1u);
        while (*(volatile unsigned*)&g_bar1 < (unsigned)TOTAL_BLOCKS)
            __nanosleep(64);
    }
    __syncthreads();
    __threadfence();                 // acquire: see all blocks' sums

    // ---------------- phase 2 ----------------
    if (w.type == 0) {
        var_impl<2, 2>(binL + (size_t)w.b * 2 * N, binLab + (size_t)w.b * N,
                       N, w.xi, w.nblk, &g_sum[0][w.b][0][0], &g_cnt[0][w.b][0],
                       &g_var2[0][w.b]);
    } else {
        var_impl<5, 6>(instL + (size_t)w.b * 5 * N, instLab + (size_t)w.b * N,
                       N, w.xi, w.nblk, &g_sum[1][w.b][0][0], &g_cnt[1][w.b][0],
                       &g_var2[1][w.b]);
    }

    // ---------------- last-block finalize ----------------
    __threadfence();
    __syncthreads();
    __shared__ bool is_last;
    if (threadIdx.x == 0) {
        unsigned v = atomicAdd(&g_done, 1u);
        is_last = (v == (unsigned)(TOTAL_BLOCKS - 1));
    }
    __syncthreads();
    if (!is_last) return;
    __threadfence();

    __shared__ float s_res[2];
    if (threadIdx.x < 8) {
        int type = threadIdx.x >> 2, b2 = threadIdx.x & 3;
        int K = type ? 6 : 2, D = type ? 5 : 2;

        float m[6][5];
        for (int k = 0; k < K; k++) {
            float cnt = g_cnt[type][b2][k];
            for (int d = 0; d < D; d++)
                m[k][d] = g_sum[type][b2][k][d] / cnt;
        }
        float l_var = g_var2[type][b2] / (float)K;

        float ld = 0.f;
        for (int i = 0; i < K; i++)
            for (int j = 0; j < K; j++) {
                if (i == j) continue;
                float sq = 0.f;
                for (int d = 0; d < D; d++) {
                    float df = m[i][d] - m[j][d];
                    sq += df * df;
                }
                float dn = fmaxf(TWO_DD - sqrtf(sq), 0.f);
                ld += dn * dn;
            }
        ld /= (float)(K * (K - 1));

        float lr = 0.f;
        for (int k = 0; k < K; k++) {
            float sq = 0.f;
            for (int d = 0; d < D; d++) sq += m[k][d] * m[k][d];
            lr += sqrtf(sq);
        }
        lr /= (float)K;

        float loss = l_var + ld + PREG * lr;
        loss += __shfl_xor_sync(0x000000ffu, loss, 1);
        loss += __shfl_xor_sync(0x000000ffu, loss, 2);
        if ((threadIdx.x & 3) == 0) s_res[type] = loss * 0.25f;
    }
    __syncthreads();
    if (threadIdx.x == 0) {
        out[0] = s_res[0];
        out[1] = s_res[1];
        g_done = 0;
        g_bar1 = 0;
    }
    // re-zero accumulators for the next graph replay
    float* p1 = &g_sum[0][0][0][0];
    for (int i = threadIdx.x; i < 2 * 4 * 8 * 8; i += blockDim.x) p1[i] = 0.f;
    float* p2 = &g_cnt[0][0][0];
    for (int i = threadIdx.x; i < 2 * 4 * 8; i += blockDim.x) p2[i] = 0.f;
    float* p3 = &g_var2[0][0];
    for (int i = threadIdx.x; i < 2 * 4; i += blockDim.x) p3[i] = 0.f;
}

// ---------------------------------------------------------------------------
extern "C" void kernel_launch(void* const* d_in, const int* in_sizes, int n_in,
                              void* d_out, int out_size) {
    const float* binL    = (const float*)d_in[0];
    const int*   binLab  = (const int*)d_in[1];
    const float* instL   = (const float*)d_in[2];
    const int*   instLab = (const int*)d_in[3];
    float* out = (float*)d_out;

    int N = in_sizes[1] / 4;  // B = 4 batches

    fused_kernel<<<TOTAL_BLOCKS, 256>>>(binL, binLab, instL, instLab, N, out);
}